// round 4
// baseline (speedup 1.0000x reference)
#include <cuda_runtime.h>
#include <math.h>

// Problem geometry (fixed): B=8, C=3, H=W=512, TILE=128, STRIDE=64
// Cells: 8x8 of 64x64 per image; tile (ty,tx) covers cells {ty,ty+1}x{tx,tx+1}.
#define BSZ   8
#define NCH   3
#define HH    512
#define WW    512
#define PLANE (HH*WW)          // 262144
#define NCELL 8
#define NTILE 7
#define INV_TILE_ELEMS (1.0f/49152.0f)   // 1/(C*128*128)

__device__ float g_cellsum[BSZ * NCELL * NCELL];
__device__ float g_lavg[BSZ * NCELL * NCELL];   // per-(b,cell) averaged logit

__device__ __forceinline__ float tanh_approx(float x) {
    float y;
    asm("tanh.approx.f32 %0, %1;" : "=f"(y) : "f"(x));
    return y;
}

// ---------------------------------------------------------------------------
// Kernel 1: per-(b, cy, cx) 64x64 cell sum of (img_c0+img_c1+img_c2) * mask.
// 512 blocks x 256 threads, float4 loads. Already at the L2 throughput cap.
// ---------------------------------------------------------------------------
__global__ void __launch_bounds__(256) cell_sum_kernel(
    const float* __restrict__ img, const float* __restrict__ mask)
{
    const int cx = blockIdx.x, cy = blockIdx.y, b = blockIdx.z;
    const int tid = threadIdx.x;

    const float* mb = mask + (b * HH + cy * 64) * WW + cx * 64;
    const float* ib = img + ((b * NCH) * HH + cy * 64) * WW + cx * 64;

    float acc = 0.0f;
    #pragma unroll
    for (int k = 0; k < 4; k++) {
        int f   = tid + k * 256;          // 0..1023 float4 slots
        int row = f >> 4;
        int col = (f & 15) << 2;
        int off = row * WW + col;
        float4 m  = *(const float4*)(mb + off);
        float4 i0 = *(const float4*)(ib + off);
        float4 i1 = *(const float4*)(ib + PLANE + off);
        float4 i2 = *(const float4*)(ib + 2 * PLANE + off);
        acc += (i0.x + i1.x + i2.x) * m.x
             + (i0.y + i1.y + i2.y) * m.y
             + (i0.z + i1.z + i2.z) * m.z
             + (i0.w + i1.w + i2.w) * m.w;
    }

    #pragma unroll
    for (int o = 16; o > 0; o >>= 1)
        acc += __shfl_xor_sync(0xffffffffu, acc, o);

    __shared__ float swarp[8];
    if ((tid & 31) == 0) swarp[tid >> 5] = acc;
    __syncthreads();
    if (tid == 0) {
        float v = swarp[0];
        #pragma unroll
        for (int w = 1; w < 8; w++) v += swarp[w];
        g_cellsum[(b * NCELL + cy) * NCELL + cx] = v;
    }
}

// ---------------------------------------------------------------------------
// Kernel 1.5: build the full per-(b,cell) averaged-logit table ONCE.
// 1 block x 512 threads; thread t handles (b = t/64, cell = t%64).
//   lavg(b,cy,cx) = mean over covering tiles (<=2x<=2) of tile logit,
//   tile logit(ty,tx) = (cs[ty,tx]+cs[ty,tx+1]+cs[ty+1,tx]+cs[ty+1,tx+1])*INV
// ---------------------------------------------------------------------------
__global__ void __launch_bounds__(512) lavg_kernel()
{
    __shared__ float cs[BSZ * NCELL * NCELL];
    const int t = threadIdx.x;
    cs[t] = g_cellsum[t];
    __syncthreads();

    const int b  = t >> 6;
    const int c  = t & 63;
    const int cy = c >> 3, cx = c & 7;
    const int ty0 = max(cy - 1, 0), ty1 = min(cy, NTILE - 1);
    const int tx0 = max(cx - 1, 0), tx1 = min(cx, NTILE - 1);

    const float* csb = cs + b * NCELL * NCELL;
    float s = 0.0f;
    for (int ty = ty0; ty <= ty1; ty++)
        for (int tx = tx0; tx <= tx1; tx++)
            s += csb[ty * NCELL + tx]       + csb[ty * NCELL + tx + 1] +
                 csb[(ty + 1) * NCELL + tx] + csb[(ty + 1) * NCELL + tx + 1];
    const float cnt = (float)((ty1 - ty0 + 1) * (tx1 - tx0 + 1));
    g_lavg[t] = s * INV_TILE_ELEMS * (1.0f / cnt);     // cnt in {1,2,4}: exact
}

// ---------------------------------------------------------------------------
// Kernel 2: pure stream — NO shared memory, NO barriers.
// Block covers an 8-row slab (4096 px), so cy is block-uniform; lavg is a
// broadcast __ldg per k. out = m*(0.5*tanh(0.25*(g + lavg*m)) + 0.5).
// ---------------------------------------------------------------------------
#define FK_IPT 4
#define FK_TPB 256
#define FK_PX_PER_BLOCK (FK_TPB * FK_IPT * 4)   // 4096 px = 8 rows

__global__ void __launch_bounds__(FK_TPB) final_kernel(
    const float* __restrict__ mask, const float* __restrict__ gmap,
    float* __restrict__ out)
{
    const int tid  = threadIdx.x;
    const int b    = blockIdx.y;
    const int base = blockIdx.x * FK_PX_PER_BLOCK;
    const int cy   = blockIdx.x >> 3;              // 8-row slab within 64-row cell
    const float* lrow = g_lavg + (b * NCELL + cy) * NCELL;

    float4 m4[FK_IPT], g4[FK_IPT];
    float  la[FK_IPT];
    int    idxv[FK_IPT];
    #pragma unroll
    for (int k = 0; k < FK_IPT; k++) {
        idxv[k] = base + (tid + k * FK_TPB) * 4;
        m4[k] = *(const float4*)(mask + b * PLANE + idxv[k]);
        g4[k] = *(const float4*)(gmap + b * PLANE + idxv[k]);
        la[k] = __ldg(lrow + ((idxv[k] & 511) >> 6));   // broadcast within warp
    }

    #pragma unroll
    for (int k = 0; k < FK_IPT; k++) {
        float4 o4;
        o4.x = m4[k].x * (0.5f * tanh_approx(0.25f * (g4[k].x + la[k] * m4[k].x)) + 0.5f);
        o4.y = m4[k].y * (0.5f * tanh_approx(0.25f * (g4[k].y + la[k] * m4[k].y)) + 0.5f);
        o4.z = m4[k].z * (0.5f * tanh_approx(0.25f * (g4[k].z + la[k] * m4[k].z)) + 0.5f);
        o4.w = m4[k].w * (0.5f * tanh_approx(0.25f * (g4[k].w + la[k] * m4[k].w)) + 0.5f);
        *(float4*)(out + b * PLANE + idxv[k]) = o4;
    }
}

// ---------------------------------------------------------------------------
// Inputs (metadata order):
//  0 image (8,3,512,512) f32 | 1 valid_mask (8,1,512,512) f32
//  2 global_heatmap (8,1,512,512) f32 | 3 tile_mask_bank (unused)
//  4 tile_mask_counts (unused) | 5 row_idx (unused) | 6 col_idx (unused)
// ---------------------------------------------------------------------------
extern "C" void kernel_launch(void* const* d_in, const int* in_sizes, int n_in,
                              void* d_out, int out_size)
{
    const float* image = (const float*)d_in[0];
    const float* mask  = (const float*)d_in[1];
    const float* gmap  = (const float*)d_in[2];
    float*       out   = (float*)d_out;

    cell_sum_kernel<<<dim3(NCELL, NCELL, BSZ), 256>>>(image, mask);
    lavg_kernel<<<1, 512>>>();
    final_kernel<<<dim3(PLANE / FK_PX_PER_BLOCK, BSZ), FK_TPB>>>(mask, gmap, out);
}

// round 5
// speedup vs baseline: 1.0201x; 1.0201x over previous
#include <cuda_runtime.h>
#include <math.h>

// Problem geometry (fixed): B=8, C=3, H=W=512, TILE=128, STRIDE=64
// Cells: 8x8 of 64x64 per image; tile (ty,tx), ty,tx in [0,7), covers cells
// {ty,ty+1}x{tx,tx+1}. counts(pixel) = (#covering ty)*(#covering tx) exactly.
#define BSZ   8
#define NCH   3
#define HH    512
#define WW    512
#define PLANE (HH*WW)          // 262144
#define NCELL 8
#define NTILE 7
#define INV_TILE_ELEMS (1.0f/49152.0f)   // 1/(C*128*128)

// Per-(b,cell) partial sums, 2 halves per cell (top/bottom 32 rows).
// Written fresh every launch -> deterministic, graph-safe, no allocation.
__device__ float g_cs2[BSZ * NCELL * NCELL * 2];

__device__ __forceinline__ float tanh_approx(float x) {
    float y;
    asm("tanh.approx.f32 %0, %1;" : "=f"(y) : "f"(x));
    return y;
}

// ---------------------------------------------------------------------------
// Kernel 1: half-cell sums of (img_c0+img_c1+img_c2)*mask.
// Block = 32 rows x 64 cols of one cell. Grid (8, 16, 8) = 1024 blocks
// (~7/SM, register-limited max) for 2x the latency hiding of R2's 512.
// ---------------------------------------------------------------------------
__global__ void __launch_bounds__(256) cell_sum_kernel(
    const float* __restrict__ img, const float* __restrict__ mask)
{
    const int cx  = blockIdx.x;
    const int cyh = blockIdx.y;            // 0..15: cell-row*2 + half
    const int b   = blockIdx.z;
    const int tid = threadIdx.x;
    const int row0 = cyh * 32;             // = cy*64 + half*32

    const float* mb = mask + (b * HH + row0) * WW + cx * 64;
    const float* ib = img + ((b * NCH) * HH + row0) * WW + cx * 64;

    float acc = 0.0f;
    #pragma unroll
    for (int k = 0; k < 2; k++) {
        int f   = tid + k * 256;           // 0..511 float4 slots (32 rows x 16)
        int row = f >> 4;
        int col = (f & 15) << 2;
        int off = row * WW + col;
        float4 m  = *(const float4*)(mb + off);
        float4 i0 = *(const float4*)(ib + off);
        float4 i1 = *(const float4*)(ib + PLANE + off);
        float4 i2 = *(const float4*)(ib + 2 * PLANE + off);
        acc += (i0.x + i1.x + i2.x) * m.x
             + (i0.y + i1.y + i2.y) * m.y
             + (i0.z + i1.z + i2.z) * m.z
             + (i0.w + i1.w + i2.w) * m.w;
    }

    #pragma unroll
    for (int o = 16; o > 0; o >>= 1)
        acc += __shfl_xor_sync(0xffffffffu, acc, o);

    __shared__ float swarp[8];
    if ((tid & 31) == 0) swarp[tid >> 5] = acc;
    __syncthreads();
    if (tid == 0) {
        float v = swarp[0];
        #pragma unroll
        for (int w = 1; w < 8; w++) v += swarp[w];
        const int cy = cyh >> 1, half = cyh & 1;
        g_cs2[(((b << 3) + cy) * NCELL + cx) * 2 + half] = v;
    }
}

// cell sum = sum of both halves (broadcast L1-hit loads)
__device__ __forceinline__ float cs_full(int b, int y, int x) {
    const float* p = g_cs2 + (((b << 3) + y) * NCELL + x) * 2;
    return __ldg(p) + __ldg(p + 1);
}

// ---------------------------------------------------------------------------
// Kernel 2: NO shared memory, NO barriers. Main float4 LDGs issue first;
// meanwhile lane l computes lavg(b, cy, l&7) from g_cs2 (broadcast L1 hits),
// and __shfl_sync distributes. Then 1 MUFU + ~4 FMA per pixel, float4 store.
// Block = 4 rows (2048 px) -> cy block-uniform. Grid (128, 8) = 1024 blocks.
// ---------------------------------------------------------------------------
#define FK_IPT 2
#define FK_TPB 256
#define FK_PX_PER_BLOCK (FK_TPB * FK_IPT * 4)   // 2048 px = 4 rows

__global__ void __launch_bounds__(FK_TPB) final_kernel(
    const float* __restrict__ mask, const float* __restrict__ gmap,
    float* __restrict__ out)
{
    const int tid  = threadIdx.x;
    const int b    = blockIdx.y;
    const int base = blockIdx.x * FK_PX_PER_BLOCK;
    const int cy   = blockIdx.x >> 4;              // 16 blocks per 64-row cell

    // ---- issue main loads FIRST ----
    float4 m4[FK_IPT], g4[FK_IPT];
    int    idxv[FK_IPT];
    #pragma unroll
    for (int k = 0; k < FK_IPT; k++) {
        idxv[k] = base + (tid + k * FK_TPB) * 4;   // float4-aligned pixel
        m4[k] = *(const float4*)(mask + b * PLANE + idxv[k]);
        g4[k] = *(const float4*)(gmap + b * PLANE + idxv[k]);
    }

    // ---- per-lane lavg for cx = lane&7 (runs under the loads; no barriers) --
    const int lane = tid & 31;
    const int cxl  = lane & 7;
    const int ty0 = max(cy - 1, 0),  ty1 = min(cy, NTILE - 1);
    const int tx0 = max(cxl - 1, 0), tx1 = min(cxl, NTILE - 1);
    float s = 0.0f;
    for (int ty = ty0; ty <= ty1; ty++)
        for (int tx = tx0; tx <= tx1; tx++)
            s += cs_full(b, ty, tx)     + cs_full(b, ty, tx + 1) +
                 cs_full(b, ty + 1, tx) + cs_full(b, ty + 1, tx + 1);
    const float cnt = (float)((ty1 - ty0 + 1) * (tx1 - tx0 + 1));  // 1,2,4
    const float lavg_l = s * INV_TILE_ELEMS * (1.0f / cnt);        // exact rcp

    // ---- main math + store ----
    #pragma unroll
    for (int k = 0; k < FK_IPT; k++) {
        int cx   = (idxv[k] & 511) >> 6;
        float la = __shfl_sync(0xffffffffu, lavg_l, cx);
        float4 o4;
        o4.x = m4[k].x * (0.5f * tanh_approx(0.25f * (g4[k].x + la * m4[k].x)) + 0.5f);
        o4.y = m4[k].y * (0.5f * tanh_approx(0.25f * (g4[k].y + la * m4[k].y)) + 0.5f);
        o4.z = m4[k].z * (0.5f * tanh_approx(0.25f * (g4[k].z + la * m4[k].z)) + 0.5f);
        o4.w = m4[k].w * (0.5f * tanh_approx(0.25f * (g4[k].w + la * m4[k].w)) + 0.5f);
        *(float4*)(out + b * PLANE + idxv[k]) = o4;
    }
}

// ---------------------------------------------------------------------------
// Inputs (metadata order):
//  0 image (8,3,512,512) f32 | 1 valid_mask (8,1,512,512) f32
//  2 global_heatmap (8,1,512,512) f32 | 3 tile_mask_bank (unused)
//  4 tile_mask_counts (unused) | 5 row_idx (unused) | 6 col_idx (unused)
// ---------------------------------------------------------------------------
extern "C" void kernel_launch(void* const* d_in, const int* in_sizes, int n_in,
                              void* d_out, int out_size)
{
    const float* image = (const float*)d_in[0];
    const float* mask  = (const float*)d_in[1];
    const float* gmap  = (const float*)d_in[2];
    float*       out   = (float*)d_out;

    cell_sum_kernel<<<dim3(NCELL, NCELL * 2, BSZ), 256>>>(image, mask);
    final_kernel<<<dim3(PLANE / FK_PX_PER_BLOCK, BSZ), FK_TPB>>>(mask, gmap, out);
}